// round 8
// baseline (speedup 1.0000x reference)
#include <cuda_runtime.h>
#include <cuda_bf16.h>
#include <math.h>
#include <stdint.h>

// ---------------- problem constants ----------------
constexpr int NCOL = 256;
constexpr int PNUM = 4096;
constexpr int ROWS = 32768;
constexpr int TM   = 128;     // M rows per CTA
constexpr int KT   = 32;      // K tile

__host__ __device__ constexpr int W1OFF(int s) {
    return s == 0 ? 0 : (s == 1 ? 98304 : 229376);
}
__host__ __device__ constexpr int W2OFF(int s) {
    return s == 0 ? 32768 : (s == 1 ? 163840 : 360448);
}
constexpr int WTOTAL = 425984;

__device__ uint4 g_whi4[WTOTAL / 8];   // transposed [n][k] bf16 hi, 32-k tiles
__device__ uint4 g_wlo4[WTOTAL / 8];   // lo residuals

// ---------------- smem word offsets ----------------
// h region: 128 x 132 words hi @0, lo @16896  (A tile 128x20 hi/lo ALIASES h-hi)
constexpr int O_SHH = 0;
constexpr int O_SHL = 16896;
constexpr int O_SXH = 0;          // alias (GEMM1 only)
constexpr int O_SXL = 2560;       // alias
constexpr int O_W   = 33792;      // 2 bufs x (hi 5120 + lo 5120)
constexpr int O_SB1 = 54272;
constexpr int O_SB2 = 54528;
constexpr int O_SSP = 54784;      // 128 rows x 4 wn
constexpr int O_PID = 55296;
constexpr int SMEM_WORDS = 55424;
constexpr int SMEM_BYTES = SMEM_WORDS * 4;   // 221,696 B

struct Params {
    const float* feat[3];
    const int*   pid[3];
    const float* w1[3];
    const float* b1[3];
    const float* w2[3];
    const float* b2[3];
    float*       out;
};

__device__ __forceinline__ uint32_t s2u(const void* p) {
    uint32_t a;
    asm("{ .reg .u64 t; cvta.to.shared.u64 t, %1; cvt.u32.u64 %0, t; }" : "=r"(a) : "l"(p));
    return a;
}
__device__ __forceinline__ void cp16(uint32_t saddr, const void* g) {
    asm volatile("cp.async.cg.shared.global [%0], [%1], 16;" :: "r"(saddr), "l"(g));
}
#define CP_COMMIT() asm volatile("cp.async.commit_group;" ::: "memory")
#define CP_WAIT0()  asm volatile("cp.async.wait_group 0;" ::: "memory")

__device__ __forceinline__ uint32_t pack_bf2(__nv_bfloat16 lo, __nv_bfloat16 hi) {
    return (uint32_t)__bfloat16_as_ushort(hi) << 16 | (uint32_t)__bfloat16_as_ushort(lo);
}
__device__ __forceinline__ void split2(float v0, float v1, uint32_t& hw, uint32_t& lw) {
    __nv_bfloat16 h0 = __float2bfloat16(v0);
    __nv_bfloat16 h1 = __float2bfloat16(v1);
    __nv_bfloat16 l0 = __float2bfloat16(v0 - __bfloat162float(h0));
    __nv_bfloat16 l1 = __float2bfloat16(v1 - __bfloat162float(h1));
    hw = pack_bf2(h0, h1);
    lw = pack_bf2(l0, l1);
}
__device__ __forceinline__ void mma16816(float* d, const uint32_t* a,
                                         uint32_t b0, uint32_t b1) {
    asm volatile(
        "mma.sync.aligned.m16n8k16.row.col.f32.bf16.bf16.f32 "
        "{%0,%1,%2,%3}, {%4,%5,%6,%7}, {%8,%9}, {%0,%1,%2,%3};"
        : "+f"(d[0]), "+f"(d[1]), "+f"(d[2]), "+f"(d[3])
        : "r"(a[0]), "r"(a[1]), "r"(a[2]), "r"(a[3]), "r"(b0), "r"(b1));
}

// ---------------- weight prep ----------------
__global__ void prep_weights(Params P)
{
    __nv_bfloat16* ghi = (__nv_bfloat16*)g_whi4;
    __nv_bfloat16* glo = (__nv_bfloat16*)g_wlo4;
    for (int m = 0; m < 6; m++) {
        int s = m >> 1;
        bool isw2 = m & 1;
        const float* w = isw2 ? P.w2[s] : P.w1[s];
        int K   = isw2 ? 256 : (128 << s);
        int off = isw2 ? W2OFF(s) : W1OFF(s);
        int nel = K * 256;
        for (int e = blockIdx.x * blockDim.x + threadIdx.x; e < nel;
             e += gridDim.x * blockDim.x) {
            int k = e >> 8, n = e & 255;
            float v = w[e];
            __nv_bfloat16 hi = __float2bfloat16(v);
            __nv_bfloat16 lo = __float2bfloat16(v - __bfloat162float(hi));
            int d = off + (k >> 5) * 8192 + n * 32 + (k & 31);
            ghi[d] = hi;
            glo[d] = lo;
        }
    }
}

// ---------------- fused kernel ----------------
__global__ void __launch_bounds__(512, 1)
fused_mma(Params P)
{
    extern __shared__ uint32_t smw[];
    uint32_t* sxh = smw + O_SXH;
    uint32_t* sxl = smw + O_SXL;
    uint32_t* shh = smw + O_SHH;
    uint32_t* shl = smw + O_SHL;
    float*    sb1 = (float*)(smw + O_SB1);
    float*    sb2 = (float*)(smw + O_SB2);
    float*    ssp = (float*)(smw + O_SSP);
    int*      spid = (int*)(smw + O_PID);
    const uint32_t smb = s2u(smw);

    const int tid  = threadIdx.x;
    const int lane = tid & 31;
    const int wid  = tid >> 5;
    const int wm   = wid & 3;          // rows wm*32..+31
    const int wn   = wid >> 2;         // cols wn*64..+63
    const int gr   = lane >> 2;
    const int c    = lane & 3;

    const int s  = blockIdx.x % 3;
    const int bi = blockIdx.x / 3;
    const int C  = 128 << s;
    const int HW = 32768 >> (2 * s);
    const int NT1 = C / KT;            // 4 / 8 / 16
    const int T   = NT1 + 8;

    const float* __restrict__ feat = P.feat[s];
    const int*   __restrict__ pid  = P.pid[s];

    const int row0 = bi * TM;
    const int b    = row0 >> 12;
    const int p0   = row0 & (PNUM - 1);

    if (tid < TM)  spid[tid] = pid[b * PNUM + p0 + tid];
    if (tid < 256) { sb1[tid] = __ldg(&P.b1[s][tid]); sb2[tid] = __ldg(&P.b2[s][tid]); }
    __syncthreads();

    const float* featb = feat + (size_t)b * C * HW;
    const __nv_bfloat16* ghi = (const __nv_bfloat16*)g_whi4;
    const __nv_bfloat16* glo = (const __nv_bfloat16*)g_wlo4;

    // gather mapping: word w -> (r = w&127, kp = w>>7); thread owns w = tid + j*512
    const int gr0 = tid & 127;
    const int kp0 = tid >> 7;          // 0..3
    const int mypid = spid[gr0];

    float acc[2][8][4];
#pragma unroll
    for (int mt = 0; mt < 2; mt++)
#pragma unroll
        for (int nt = 0; nt < 8; nt++)
#pragma unroll
            for (int q = 0; q < 4; q++) acc[mt][nt][q] = 0.f;

    float va[8];                       // A gather prefetch

    // issue cp.async W(0) into buf0 + gather tile 0
    {
        const char* srch = (const char*)(ghi + W1OFF(s));
        const char* srcl = (const char*)(glo + W1OFF(s));
        const uint32_t wh0 = smb + O_W * 4;
        const uint32_t wl0 = wh0 + 5120 * 4;
#pragma unroll
        for (int j = 0; j < 2; j++) {
            int u = tid + j * 512;
            uint32_t doff = (u >> 2) * 80 + (u & 3) * 16;
            cp16(wh0 + doff, srch + (size_t)u * 16);
            cp16(wl0 + doff, srcl + (size_t)u * 16);
        }
        CP_COMMIT();
#pragma unroll
        for (int j = 0; j < 4; j++) {
            int k = (kp0 + 4 * j) * 2;
            va[2 * j]     = __ldg(&featb[(size_t)k * HW + mypid]);
            va[2 * j + 1] = __ldg(&featb[(size_t)(k + 1) * HW + mypid]);
        }
    }

    for (int t = 0; t < T; t++) {
        // ---- GEMM1->GEMM2 boundary: write h (aliases A; prior sync protects) ----
        if (t == NT1) {
#pragma unroll
            for (int mt = 0; mt < 2; mt++) {
                const int rH = wm * 32 + mt * 16 + gr;
#pragma unroll
                for (int nt = 0; nt < 8; nt++) {
                    const int n  = wn * 64 + nt * 8 + 2 * c;
                    const int wi = wn * 32 + nt * 4 + c;
                    float v0 = fmaxf(acc[mt][nt][0] + sb1[n],     0.f);
                    float v1 = fmaxf(acc[mt][nt][1] + sb1[n + 1], 0.f);
                    float v2 = fmaxf(acc[mt][nt][2] + sb1[n],     0.f);
                    float v3 = fmaxf(acc[mt][nt][3] + sb1[n + 1], 0.f);
                    uint32_t hw, lw;
                    split2(v0, v1, hw, lw);
                    shh[rH * 132 + wi] = hw;
                    shl[rH * 132 + wi] = lw;
                    split2(v2, v3, hw, lw);
                    shh[(rH + 8) * 132 + wi] = hw;
                    shl[(rH + 8) * 132 + wi] = lw;
#pragma unroll
                    for (int q = 0; q < 4; q++) acc[mt][nt][q] = 0.f;
                }
            }
        }
        // ---- store gathered A for this tile ----
        if (t < NT1) {
#pragma unroll
            for (int j = 0; j < 4; j++) {
                uint32_t hw, lw;
                split2(va[2 * j], va[2 * j + 1], hw, lw);
                sxh[gr0 * 20 + kp0 + 4 * j] = hw;
                sxl[gr0 * 20 + kp0 + 4 * j] = lw;
            }
        }
        CP_WAIT0();           // W(t) landed
        __syncthreads();

        // ---- issue W(t+1) into other buffer; gather va(t+1) ----
        if (t + 1 < T) {
            const int woff = (t + 1 < NT1) ? (W1OFF(s) + (t + 1) * 8192)
                                           : (W2OFF(s) + (t + 1 - NT1) * 8192);
            const char* srch = (const char*)(ghi + woff);
            const char* srcl = (const char*)(glo + woff);
            const uint32_t whn = smb + (O_W + ((t + 1) & 1) * 10240) * 4;
            const uint32_t wln = whn + 5120 * 4;
#pragma unroll
            for (int j = 0; j < 2; j++) {
                int u = tid + j * 512;
                uint32_t doff = (u >> 2) * 80 + (u & 3) * 16;
                cp16(whn + doff, srch + (size_t)u * 16);
                cp16(wln + doff, srcl + (size_t)u * 16);
            }
            CP_COMMIT();
        }
        if (t + 1 < NT1) {
#pragma unroll
            for (int j = 0; j < 4; j++) {
                int k = (t + 1) * KT + (kp0 + 4 * j) * 2;
                va[2 * j]     = __ldg(&featb[(size_t)k * HW + mypid]);
                va[2 * j + 1] = __ldg(&featb[(size_t)(k + 1) * HW + mypid]);
            }
        }

        // ---- MMA phase ----
        const uint32_t* wh = smw + O_W + (t & 1) * 10240;
        const uint32_t* wl = wh + 5120;
#pragma unroll
        for (int ks = 0; ks < 2; ks++) {
            uint32_t ah[2][4], al[2][4];
            if (t < NT1) {
#pragma unroll
                for (int mt = 0; mt < 2; mt++) {
                    const int ab = (wm * 32 + mt * 16 + gr) * 20 + ks * 8 + c;
                    ah[mt][0] = sxh[ab];       ah[mt][1] = sxh[ab + 160];
                    ah[mt][2] = sxh[ab + 4];   ah[mt][3] = sxh[ab + 164];
                    al[mt][0] = sxl[ab];       al[mt][1] = sxl[ab + 160];
                    al[mt][2] = sxl[ab + 4];   al[mt][3] = sxl[ab + 164];
                }
            } else {
                const int tt = t - NT1;
#pragma unroll
                for (int mt = 0; mt < 2; mt++) {
                    const int ab = (wm * 32 + mt * 16 + gr) * 132 + tt * 16 + ks * 8 + c;
                    ah[mt][0] = shh[ab];        ah[mt][1] = shh[ab + 1056];
                    ah[mt][2] = shh[ab + 4];    ah[mt][3] = shh[ab + 1060];
                    al[mt][0] = shl[ab];        al[mt][1] = shl[ab + 1056];
                    al[mt][2] = shl[ab + 4];    al[mt][3] = shl[ab + 1060];
                }
            }
#pragma unroll
            for (int nt = 0; nt < 8; nt++) {
                const int bb = (wn * 64 + nt * 8 + gr) * 20 + ks * 8 + c;
                uint32_t bh0 = wh[bb], bh1 = wh[bb + 4];
                uint32_t bl0 = wl[bb], bl1 = wl[bb + 4];
#pragma unroll
                for (int mt = 0; mt < 2; mt++) {
                    mma16816(acc[mt][nt], ah[mt], bh0, bh1);
                    mma16816(acc[mt][nt], ah[mt], bl0, bl1);
                    mma16816(acc[mt][nt], al[mt], bh0, bh1);
                }
            }
        }
        __syncthreads();
    }

    // ================= epilogue: +b2, L2 normalize, store =================
    float ss[2][2];
#pragma unroll
    for (int mt = 0; mt < 2; mt++) {
        ss[mt][0] = 0.f; ss[mt][1] = 0.f;
#pragma unroll
        for (int nt = 0; nt < 8; nt++) {
            const int n = wn * 64 + nt * 8 + 2 * c;
            acc[mt][nt][0] += sb2[n];
            acc[mt][nt][1] += sb2[n + 1];
            acc[mt][nt][2] += sb2[n];
            acc[mt][nt][3] += sb2[n + 1];
            ss[mt][0] = fmaf(acc[mt][nt][0], acc[mt][nt][0],
                        fmaf(acc[mt][nt][1], acc[mt][nt][1], ss[mt][0]));
            ss[mt][1] = fmaf(acc[mt][nt][2], acc[mt][nt][2],
                        fmaf(acc[mt][nt][3], acc[mt][nt][3], ss[mt][1]));
        }
#pragma unroll
        for (int h = 0; h < 2; h++) {
            ss[mt][h] += __shfl_xor_sync(0xffffffffu, ss[mt][h], 1);
            ss[mt][h] += __shfl_xor_sync(0xffffffffu, ss[mt][h], 2);
        }
        if (c == 0) {
            const int rE = wm * 32 + mt * 16 + gr;
            ssp[rE * 4 + wn]       = ss[mt][0];
            ssp[(rE + 8) * 4 + wn] = ss[mt][1];
        }
    }
    __syncthreads();

    float* __restrict__ out = P.out + ((size_t)s * ROWS + row0) * NCOL;
#pragma unroll
    for (int mt = 0; mt < 2; mt++) {
        const int rE = wm * 32 + mt * 16 + gr;
        const float inv0 = 1.f / (sqrtf(ssp[rE * 4] + ssp[rE * 4 + 1] +
                                        ssp[rE * 4 + 2] + ssp[rE * 4 + 3]) + 1e-7f);
        const float inv1 = 1.f / (sqrtf(ssp[(rE + 8) * 4] + ssp[(rE + 8) * 4 + 1] +
                                        ssp[(rE + 8) * 4 + 2] + ssp[(rE + 8) * 4 + 3]) + 1e-7f);
#pragma unroll
        for (int nt = 0; nt < 8; nt++) {
            const int n = wn * 64 + nt * 8 + 2 * c;
            float2 o0 = make_float2(acc[mt][nt][0] * inv0, acc[mt][nt][1] * inv0);
            float2 o1 = make_float2(acc[mt][nt][2] * inv1, acc[mt][nt][3] * inv1);
            *(float2*)&out[(size_t)rE * NCOL + n]       = o0;
            *(float2*)&out[(size_t)(rE + 8) * NCOL + n] = o1;
        }
    }
}

// ---------------- launch ----------------
extern "C" void kernel_launch(void* const* d_in, const int* in_sizes, int n_in,
                              void* d_out, int out_size)
{
    const bool sig_order = (n_in > 1) && (in_sizes[1] == 16777216);

    Params P;
    if (sig_order) {
        for (int s = 0; s < 3; s++) {
            P.feat[s] = (const float*)d_in[s];
            P.pid[s]  = (const int*)  d_in[3 + s];
            P.w1[s]   = (const float*)d_in[6 + 4 * s];
            P.b1[s]   = (const float*)d_in[7 + 4 * s];
            P.w2[s]   = (const float*)d_in[8 + 4 * s];
            P.b2[s]   = (const float*)d_in[9 + 4 * s];
        }
    } else {
        for (int s = 0; s < 3; s++) {
            P.feat[s] = (const float*)d_in[6 * s + 0];
            P.pid[s]  = (const int*)  d_in[6 * s + 1];
            P.w1[s]   = (const float*)d_in[6 * s + 2];
            P.b1[s]   = (const float*)d_in[6 * s + 3];
            P.w2[s]   = (const float*)d_in[6 * s + 4];
            P.b2[s]   = (const float*)d_in[6 * s + 5];
        }
    }
    P.out = (float*)d_out;

    cudaFuncSetAttribute(fused_mma, cudaFuncAttributeMaxDynamicSharedMemorySize,
                         SMEM_BYTES);

    prep_weights<<<256, 256>>>(P);
    fused_mma<<<3 * (ROWS / TM), 512, SMEM_BYTES>>>(P);
}

// round 9
// speedup vs baseline: 1.4811x; 1.4811x over previous
#include <cuda_runtime.h>
#include <cuda_bf16.h>
#include <math.h>
#include <stdint.h>

// ---------------- problem constants ----------------
constexpr int NCOL = 256;
constexpr int PNUM = 4096;
constexpr int ROWS = 32768;
constexpr int TM   = 64;      // M rows per CTA
constexpr int KT   = 32;      // K tile

__host__ __device__ constexpr int W1OFF(int s) {
    return s == 0 ? 0 : (s == 1 ? 98304 : 229376);
}
__host__ __device__ constexpr int W2OFF(int s) {
    return s == 0 ? 32768 : (s == 1 ? 163840 : 360448);
}
constexpr int WTOTAL = 425984;

__device__ uint4 g_whi4[WTOTAL / 8];   // transposed [n][k] bf16 hi, 32-k tiles
__device__ uint4 g_wlo4[WTOTAL / 8];   // lo residuals

// ---------------- smem word offsets ----------------
constexpr int O_SXH = 0;          // A hi: 64 x 20 words
constexpr int O_SXL = 1280;
constexpr int O_SWH = 2560;       // W hi: 256 x 20 words
constexpr int O_SWL = 7680;
constexpr int O_SHH = 12800;      // h hi: 64 x 132 words
constexpr int O_SHL = 21248;
constexpr int O_SB1 = 29696;
constexpr int O_SB2 = 29952;
constexpr int O_SSP = 30208;
constexpr int O_PID = 30464;
constexpr int SMEM_WORDS = 30528;
constexpr int SMEM_BYTES = SMEM_WORDS * 4;   // 122,112 B

struct Params {
    const float* feat[3];
    const int*   pid[3];
    const float* w1[3];
    const float* b1[3];
    const float* w2[3];
    const float* b2[3];
    float*       out;
};

__device__ __forceinline__ uint32_t s2u(const void* p) {
    uint32_t a;
    asm("{ .reg .u64 t; cvta.to.shared.u64 t, %1; cvt.u32.u64 %0, t; }" : "=r"(a) : "l"(p));
    return a;
}
__device__ __forceinline__ uint32_t pack_bf2(__nv_bfloat16 lo, __nv_bfloat16 hi) {
    return (uint32_t)__bfloat16_as_ushort(hi) << 16 | (uint32_t)__bfloat16_as_ushort(lo);
}
__device__ __forceinline__ void split2(float v0, float v1, uint32_t& hw, uint32_t& lw) {
    __nv_bfloat16 h0 = __float2bfloat16(v0);
    __nv_bfloat16 h1 = __float2bfloat16(v1);
    __nv_bfloat16 l0 = __float2bfloat16(v0 - __bfloat162float(h0));
    __nv_bfloat16 l1 = __float2bfloat16(v1 - __bfloat162float(h1));
    hw = pack_bf2(h0, h1);
    lw = pack_bf2(l0, l1);
}
__device__ __forceinline__ void mma16816(float* d, const uint32_t* a,
                                         uint32_t b0, uint32_t b1) {
    asm volatile(
        "mma.sync.aligned.m16n8k16.row.col.f32.bf16.bf16.f32 "
        "{%0,%1,%2,%3}, {%4,%5,%6,%7}, {%8,%9}, {%0,%1,%2,%3};"
        : "+f"(d[0]), "+f"(d[1]), "+f"(d[2]), "+f"(d[3])
        : "r"(a[0]), "r"(a[1]), "r"(a[2]), "r"(a[3]), "r"(b0), "r"(b1));
}
#define LDMX4(r0, r1, r2, r3, addr)                                           \
    asm volatile("ldmatrix.sync.aligned.m8n8.x4.shared.b16 {%0,%1,%2,%3}, [%4];" \
        : "=r"(r0), "=r"(r1), "=r"(r2), "=r"(r3) : "r"(addr))

// ---------------- weight prep ----------------
__global__ void prep_weights(Params P)
{
    __nv_bfloat16* ghi = (__nv_bfloat16*)g_whi4;
    __nv_bfloat16* glo = (__nv_bfloat16*)g_wlo4;
    for (int m = 0; m < 6; m++) {
        int s = m >> 1;
        bool isw2 = m & 1;
        const float* w = isw2 ? P.w2[s] : P.w1[s];
        int K   = isw2 ? 256 : (128 << s);
        int off = isw2 ? W2OFF(s) : W1OFF(s);
        int nel = K * 256;
        for (int e = blockIdx.x * blockDim.x + threadIdx.x; e < nel;
             e += gridDim.x * blockDim.x) {
            int k = e >> 8, n = e & 255;
            float v = w[e];
            __nv_bfloat16 hi = __float2bfloat16(v);
            __nv_bfloat16 lo = __float2bfloat16(v - __bfloat162float(hi));
            int d = off + (k >> 5) * 8192 + n * 32 + (k & 31);
            ghi[d] = hi;
            glo[d] = lo;
        }
    }
}

// ---------------- fused kernel: 512 thr, reg-prefetch + ldmatrix ----------------
__global__ void __launch_bounds__(512, 1)
fused_mma(Params P)
{
    extern __shared__ uint32_t smw[];
    uint32_t* sxh = smw + O_SXH;
    uint32_t* sxl = smw + O_SXL;
    float*    sb1 = (float*)(smw + O_SB1);
    float*    sb2 = (float*)(smw + O_SB2);
    float*    ssp = (float*)(smw + O_SSP);
    int*      spid = (int*)(smw + O_PID);
    const uint32_t smb = s2u(smw);

    const int tid  = threadIdx.x;
    const int lane = tid & 31;
    const int wid  = tid >> 5;
    const int wm   = wid & 3;          // rows wm*16..+15
    const int wn   = wid >> 2;         // cols wn*64..+63
    const int gr   = lane >> 2;
    const int c    = lane & 3;
    const int rowA = wm * 16 + gr;
    const int lr   = lane & 15;        // ldmatrix row-provider index
    const int lh   = lane >> 4;        // ldmatrix k-half

    const int s  = blockIdx.x % 3;
    const int bi = blockIdx.x / 3;
    const int C  = 128 << s;
    const int HW = 32768 >> (2 * s);
    const int NT1 = C / KT;            // 4 / 8 / 16
    const int T   = NT1 + 8;

    const float* __restrict__ feat = P.feat[s];
    const int*   __restrict__ pid  = P.pid[s];

    const int row0 = bi * TM;
    const int b    = row0 >> 12;
    const int p0   = row0 & (PNUM - 1);

    if (tid < TM)  spid[tid] = pid[b * PNUM + p0 + tid];
    if (tid < 256) { sb1[tid] = __ldg(&P.b1[s][tid]); sb2[tid] = __ldg(&P.b2[s][tid]); }
    __syncthreads();

    const float* featb = feat + (size_t)b * C * HW;
    const __nv_bfloat16* ghi = (const __nv_bfloat16*)g_whi4;
    const __nv_bfloat16* glo = (const __nv_bfloat16*)g_wlo4;

    const int gr0 = tid & 63;
    const int gkp = tid >> 6;          // 0..7
    const int mypid = spid[gr0];

    float acc[8][4];
#pragma unroll
    for (int nt = 0; nt < 8; nt++)
#pragma unroll
        for (int q = 0; q < 4; q++) acc[nt][q] = 0.f;

    uint4 pwh0, pwh1, pwl0, pwl1;      // W prefetch regs
    float va0, va1, va2, va3;          // A gather prefetch regs

    // ---- prologue: prefetch tile 0 ----
    {
        const uint4* srch = (const uint4*)(ghi + W1OFF(s));
        const uint4* srcl = (const uint4*)(glo + W1OFF(s));
        pwh0 = __ldg(&srch[tid]);  pwh1 = __ldg(&srch[tid + 512]);
        pwl0 = __ldg(&srcl[tid]);  pwl1 = __ldg(&srcl[tid + 512]);
        int k = gkp * 2;
        va0 = __ldg(&featb[(size_t)k * HW + mypid]);
        va1 = __ldg(&featb[(size_t)(k + 1) * HW + mypid]);
        int k2 = (gkp + 8) * 2;
        va2 = __ldg(&featb[(size_t)k2 * HW + mypid]);
        va3 = __ldg(&featb[(size_t)(k2 + 1) * HW + mypid]);
    }

    // ldmatrix base addresses (byte), k-dependent offsets added per use
    const uint32_t adrB_h = smb + (O_SWH + (wn * 64 + lr) * 20 + lh * 4) * 4;
    const uint32_t adrB_l = smb + (O_SWL + (wn * 64 + lr) * 20 + lh * 4) * 4;
    const uint32_t adrA1_h = smb + (O_SXH + (wm * 16 + lr) * 20 + lh * 4) * 4;
    const uint32_t adrA1_l = smb + (O_SXL + (wm * 16 + lr) * 20 + lh * 4) * 4;
    const uint32_t adrA2_h = smb + (O_SHH + (wm * 16 + lr) * 132 + lh * 4) * 4;
    const uint32_t adrA2_l = smb + (O_SHL + (wm * 16 + lr) * 132 + lh * 4) * 4;

    for (int t = 0; t < T; t++) {
        // ---- store prefetched tile into smem ----
        {
            int n0 = tid >> 2, q0 = tid & 3;
            int u1 = tid + 512;
            int n1 = u1 >> 2, q1 = u1 & 3;
            uint32_t* swh = smw + O_SWH;
            uint32_t* swl = smw + O_SWL;
            *(uint4*)((char*)swh + n0 * 80 + q0 * 16) = pwh0;
            *(uint4*)((char*)swh + n1 * 80 + q1 * 16) = pwh1;
            *(uint4*)((char*)swl + n0 * 80 + q0 * 16) = pwl0;
            *(uint4*)((char*)swl + n1 * 80 + q1 * 16) = pwl1;
        }
        if (t < NT1) {
            uint32_t hw, lw;
            split2(va0, va1, hw, lw);
            sxh[gr0 * 20 + gkp] = hw;
            sxl[gr0 * 20 + gkp] = lw;
            split2(va2, va3, hw, lw);
            sxh[gr0 * 20 + gkp + 8] = hw;
            sxl[gr0 * 20 + gkp + 8] = lw;
        }
        __syncthreads();

        // ---- prefetch tile t+1 (overlaps with MMA below) ----
        if (t + 1 < T) {
            const int woff = (t + 1 < NT1) ? (W1OFF(s) + (t + 1) * 8192)
                                           : (W2OFF(s) + (t + 1 - NT1) * 8192);
            const uint4* srch = (const uint4*)(ghi + woff);
            const uint4* srcl = (const uint4*)(glo + woff);
            pwh0 = __ldg(&srch[tid]);  pwh1 = __ldg(&srch[tid + 512]);
            pwl0 = __ldg(&srcl[tid]);  pwl1 = __ldg(&srcl[tid + 512]);
        }
        if (t + 1 < NT1) {
            int k = (t + 1) * KT + gkp * 2;
            va0 = __ldg(&featb[(size_t)k * HW + mypid]);
            va1 = __ldg(&featb[(size_t)(k + 1) * HW + mypid]);
            int k2 = (t + 1) * KT + (gkp + 8) * 2;
            va2 = __ldg(&featb[(size_t)k2 * HW + mypid]);
            va3 = __ldg(&featb[(size_t)(k2 + 1) * HW + mypid]);
        }

        // ---- MMA phase (ldmatrix fragments) ----
#pragma unroll
        for (int ks = 0; ks < 2; ks++) {
            uint32_t ah[4], al[4];
            if (t < NT1) {
                LDMX4(ah[0], ah[1], ah[2], ah[3], adrA1_h + ks * 32);
                LDMX4(al[0], al[1], al[2], al[3], adrA1_l + ks * 32);
            } else {
                const uint32_t koff = (uint32_t)(t - NT1) * 64 + ks * 32;
                LDMX4(ah[0], ah[1], ah[2], ah[3], adrA2_h + koff);
                LDMX4(al[0], al[1], al[2], al[3], adrA2_l + koff);
            }
#pragma unroll
            for (int p = 0; p < 4; p++) {
                // nt pair (2p, 2p+1): 16 n-rows via one x4 each for hi and lo
                uint32_t bh[4], bl[4];
                const uint32_t boff = (uint32_t)p * 16 * 80 + ks * 32;
                LDMX4(bh[0], bh[1], bh[2], bh[3], adrB_h + boff);
                LDMX4(bl[0], bl[1], bl[2], bl[3], adrB_l + boff);
                mma16816(acc[2 * p],     ah, bh[0], bh[2]);
                mma16816(acc[2 * p],     ah, bl[0], bl[2]);
                mma16816(acc[2 * p],     al, bh[0], bh[2]);
                mma16816(acc[2 * p + 1], ah, bh[1], bh[3]);
                mma16816(acc[2 * p + 1], ah, bl[1], bl[3]);
                mma16816(acc[2 * p + 1], al, bh[1], bh[3]);
            }
        }

        // ---- GEMM1->GEMM2 boundary: h epilogue ----
        if (t == NT1 - 1) {
            uint32_t* shh = smw + O_SHH;
            uint32_t* shl = smw + O_SHL;
#pragma unroll
            for (int nt = 0; nt < 8; nt++) {
                const int n  = wn * 64 + nt * 8 + 2 * c;
                const int wi = wn * 32 + nt * 4 + c;
                float v0 = fmaxf(acc[nt][0] + sb1[n],     0.f);
                float v1 = fmaxf(acc[nt][1] + sb1[n + 1], 0.f);
                float v2 = fmaxf(acc[nt][2] + sb1[n],     0.f);
                float v3 = fmaxf(acc[nt][3] + sb1[n + 1], 0.f);
                uint32_t hw, lw;
                split2(v0, v1, hw, lw);
                shh[rowA * 132 + wi] = hw;
                shl[rowA * 132 + wi] = lw;
                split2(v2, v3, hw, lw);
                shh[(rowA + 8) * 132 + wi] = hw;
                shl[(rowA + 8) * 132 + wi] = lw;
#pragma unroll
                for (int q = 0; q < 4; q++) acc[nt][q] = 0.f;
            }
        }
        __syncthreads();
    }

    // ================= epilogue: +b2, L2 normalize, store =================
    float ss0 = 0.f, ss1 = 0.f;
#pragma unroll
    for (int nt = 0; nt < 8; nt++) {
        const int n = wn * 64 + nt * 8 + 2 * c;
        acc[nt][0] += sb2[n];
        acc[nt][1] += sb2[n + 1];
        acc[nt][2] += sb2[n];
        acc[nt][3] += sb2[n + 1];
        ss0 = fmaf(acc[nt][0], acc[nt][0], fmaf(acc[nt][1], acc[nt][1], ss0));
        ss1 = fmaf(acc[nt][2], acc[nt][2], fmaf(acc[nt][3], acc[nt][3], ss1));
    }
    ss0 += __shfl_xor_sync(0xffffffffu, ss0, 1);
    ss0 += __shfl_xor_sync(0xffffffffu, ss0, 2);
    ss1 += __shfl_xor_sync(0xffffffffu, ss1, 1);
    ss1 += __shfl_xor_sync(0xffffffffu, ss1, 2);
    if (c == 0) {
        ssp[rowA * 4 + wn]       = ss0;
        ssp[(rowA + 8) * 4 + wn] = ss1;
    }
    __syncthreads();
    const float inv0 = 1.f / (sqrtf(ssp[rowA * 4] + ssp[rowA * 4 + 1] +
                                    ssp[rowA * 4 + 2] + ssp[rowA * 4 + 3]) + 1e-7f);
    const float inv1 = 1.f / (sqrtf(ssp[(rowA + 8) * 4] + ssp[(rowA + 8) * 4 + 1] +
                                    ssp[(rowA + 8) * 4 + 2] + ssp[(rowA + 8) * 4 + 3]) + 1e-7f);

    float* __restrict__ out = P.out + ((size_t)s * ROWS + row0) * NCOL;
#pragma unroll
    for (int nt = 0; nt < 8; nt++) {
        const int n = wn * 64 + nt * 8 + 2 * c;
        float2 o0 = make_float2(acc[nt][0] * inv0, acc[nt][1] * inv0);
        float2 o1 = make_float2(acc[nt][2] * inv1, acc[nt][3] * inv1);
        *(float2*)&out[(size_t)rowA * NCOL + n]       = o0;
        *(float2*)&out[(size_t)(rowA + 8) * NCOL + n] = o1;
    }
}

// ---------------- launch ----------------
extern "C" void kernel_launch(void* const* d_in, const int* in_sizes, int n_in,
                              void* d_out, int out_size)
{
    const bool sig_order = (n_in > 1) && (in_sizes[1] == 16777216);

    Params P;
    if (sig_order) {
        for (int s = 0; s < 3; s++) {
            P.feat[s] = (const float*)d_in[s];
            P.pid[s]  = (const int*)  d_in[3 + s];
            P.w1[s]   = (const float*)d_in[6 + 4 * s];
            P.b1[s]   = (const float*)d_in[7 + 4 * s];
            P.w2[s]   = (const float*)d_in[8 + 4 * s];
            P.b2[s]   = (const float*)d_in[9 + 4 * s];
        }
    } else {
        for (int s = 0; s < 3; s++) {
            P.feat[s] = (const float*)d_in[6 * s + 0];
            P.pid[s]  = (const int*)  d_in[6 * s + 1];
            P.w1[s]   = (const float*)d_in[6 * s + 2];
            P.b1[s]   = (const float*)d_in[6 * s + 3];
            P.w2[s]   = (const float*)d_in[6 * s + 4];
            P.b2[s]   = (const float*)d_in[6 * s + 5];
        }
    }
    P.out = (float*)d_out;

    cudaFuncSetAttribute(fused_mma, cudaFuncAttributeMaxDynamicSharedMemorySize,
                         SMEM_BYTES);

    prep_weights<<<256, 256>>>(P);
    fused_mma<<<3 * (ROWS / TM), 512, SMEM_BYTES>>>(P);
}